// round 5
// baseline (speedup 1.0000x reference)
#include <cuda_runtime.h>
#include <math.h>

// Problem constants
#define BATCH 2
#define SEQ   2048
#define DM    1024
#define NH    16
#define DK    64
#define MTOT  (BATCH*SEQ)       // 4096

// ---------------- scratch (no allocations allowed) ----------------
__device__ float g_Qh [BATCH*NH*SEQ*DK];   // [b*h][s][dk], pre-scaled by 1/8
__device__ float g_KhT[BATCH*NH*DK*SEQ];   // [b*h][dk][s]  (transposed K heads)
__device__ float g_Vh [BATCH*NH*SEQ*DK];   // [b*h][s][dk]
__device__ float g_At [MTOT*DM];           // attention output, [b*s][h*dk]

// ---------------- tiled fp32 GEMM: Y = X(MxK) @ W(KxN) (+bias) ----------------
// mode 0: plain Y[m][n] (+bias)
// mode 1: head layout [b*h][s][dk], (+bias), * 0.125   (Q)
// mode 2: transposed head layout [b*h][dk][s], no bias (K)
// mode 3: head layout [b*h][s][dk], (+bias)            (V)
#define GBM 128
#define GBN 128
#define GBK 16

__global__ __launch_bounds__(256)
void gemm_kernel(const float* __restrict__ X, const float* __restrict__ W,
                 const float* __restrict__ bias, float* __restrict__ Y,
                 int M, int N, int K, int mode)
{
    __shared__ float As[GBK][GBM];   // A stored transposed: As[k][m]
    __shared__ float Bs[GBK][GBN];

    const int tid = threadIdx.x;
    const int tx  = tid & 15;
    const int ty  = tid >> 4;
    const int bm  = blockIdx.y * GBM;
    const int bn  = blockIdx.x * GBN;

    float acc[8][8];
#pragma unroll
    for (int i = 0; i < 8; i++)
#pragma unroll
        for (int j = 0; j < 8; j++) acc[i][j] = 0.f;

    for (int k0 = 0; k0 < K; k0 += GBK) {
        // load A tile 128x16 (512 float4)
#pragma unroll
        for (int r = 0; r < 2; r++) {
            int s   = tid + r * 256;
            int row = s >> 2;
            int c4  = s & 3;
            float4 a = *(const float4*)&X[(bm + row) * K + k0 + c4 * 4];
            As[c4 * 4 + 0][row] = a.x;
            As[c4 * 4 + 1][row] = a.y;
            As[c4 * 4 + 2][row] = a.z;
            As[c4 * 4 + 3][row] = a.w;
        }
        // load B tile 16x128 (512 float4)
#pragma unroll
        for (int r = 0; r < 2; r++) {
            int s   = tid + r * 256;
            int row = s >> 5;
            int c4  = s & 31;
            *(float4*)&Bs[row][c4 * 4] = *(const float4*)&W[(k0 + row) * N + bn + c4 * 4];
        }
        __syncthreads();

#pragma unroll
        for (int kk = 0; kk < GBK; kk++) {
            float af[8], bv[8];
            *(float4*)&af[0] = *(float4*)&As[kk][ty * 8];
            *(float4*)&af[4] = *(float4*)&As[kk][ty * 8 + 4];
            *(float4*)&bv[0] = *(float4*)&Bs[kk][tx * 8];
            *(float4*)&bv[4] = *(float4*)&Bs[kk][tx * 8 + 4];
#pragma unroll
            for (int i = 0; i < 8; i++)
#pragma unroll
                for (int j = 0; j < 8; j++)
                    acc[i][j] += af[i] * bv[j];
        }
        __syncthreads();
    }

    // epilogue
#pragma unroll
    for (int i = 0; i < 8; i++) {
        int m = bm + ty * 8 + i;
#pragma unroll
        for (int j = 0; j < 8; j++) {
            int n = bn + tx * 8 + j;
            float v = acc[i][j];
            if (bias) v += bias[n];
            if (mode == 1) v *= 0.125f;   // 1/sqrt(d_k)
            int idx;
            if (mode == 0) {
                idx = m * N + n;
            } else {
                int b  = m >> 11;        // / SEQ
                int s  = m & (SEQ - 1);
                int h  = n >> 6;         // / DK
                int dk = n & (DK - 1);
                if (mode == 2)
                    idx = ((b * NH + h) * DK + dk) * SEQ + s;
                else
                    idx = ((b * NH + h) * SEQ + s) * DK + dk;
            }
            Y[idx] = v;
        }
    }
}

// ---------------- flash attention (fp32, online softmax) ----------------
// grid: (SEQ/64, BATCH*NH). block: 256 threads (16x16), each thread owns
// a 4(row)x4(col) micro-tile of the 64x64 score tile and a 4x4 O micro-tile.
#define PSTR 68

__global__ __launch_bounds__(256)
void attn_kernel(const float* __restrict__ Qh, const float* __restrict__ KhT,
                 const float* __restrict__ Vh, const int* __restrict__ mask,
                 float* __restrict__ Out)
{
    extern __shared__ float sm[];
    float* Qs = sm;                  // [64][64]
    float* Ks = sm + 64 * 64;        // K^T tile [64 d][64 c]
    float* Vs = sm + 2 * 64 * 64;    // [64 j][64 d]
    float* Ps = sm + 3 * 64 * 64;    // [64][PSTR]

    const int tid = threadIdx.x;
    const int tx  = tid & 15;
    const int ty  = tid >> 4;
    const int qt  = blockIdx.x;      // query tile
    const int bh  = blockIdx.y;      // b*NH + h
    const int b   = bh >> 4;

    const float* Qbase = Qh  + (bh * SEQ + qt * 64) * DK;   // 64x64 contiguous
    const float* Kbase = KhT + bh * DK * SEQ;
    const float* Vbase = Vh  + bh * SEQ * DK;
    const int*   Mbase = mask + (b * SEQ + qt * 64) * SEQ;

    // load Q tile (contiguous 4096 floats)
#pragma unroll
    for (int r = 0; r < 4; r++) {
        int s = tid + r * 256;
        ((float4*)Qs)[s] = ((const float4*)Qbase)[s];
    }

    float m_run[4], l_run[4], o[4][4];
#pragma unroll
    for (int i = 0; i < 4; i++) {
        m_run[i] = -1e38f;
        l_run[i] = 0.f;
#pragma unroll
        for (int j = 0; j < 4; j++) o[i][j] = 0.f;
    }

    for (int kt = 0; kt < SEQ / 64; kt++) {
        __syncthreads();   // protect Ks/Vs (prev PV done) and Q on first iter
        // load K^T tile: rows d (stride SEQ), cols kt*64..
#pragma unroll
        for (int r = 0; r < 4; r++) {
            int s  = tid + r * 256;
            int d  = s >> 4;
            int c4 = s & 15;
            *(float4*)&Ks[d * 64 + c4 * 4] =
                *(const float4*)&Kbase[d * SEQ + kt * 64 + c4 * 4];
        }
        // load V tile (contiguous 4096 floats)
        const float4* vsrc = (const float4*)(Vbase + kt * 64 * DK);
#pragma unroll
        for (int r = 0; r < 4; r++) {
            int s = tid + r * 256;
            ((float4*)Vs)[s] = vsrc[s];
        }
        __syncthreads();

        // scores: sc[i][j] = sum_d Q[row_i][d] * K^T[d][col_j]
        float sc[4][4];
#pragma unroll
        for (int i = 0; i < 4; i++)
#pragma unroll
            for (int j = 0; j < 4; j++) sc[i][j] = 0.f;

#pragma unroll 16
        for (int d = 0; d < 64; d++) {
            float qv[4], kv[4];
#pragma unroll
            for (int i = 0; i < 4; i++) qv[i] = Qs[(ty * 4 + i) * 64 + d];
            *(float4*)kv = *(float4*)&Ks[d * 64 + tx * 4];
#pragma unroll
            for (int i = 0; i < 4; i++)
#pragma unroll
                for (int j = 0; j < 4; j++)
                    sc[i][j] += qv[i] * kv[j];
        }

        // mask (mask==0 -> -inf before softmax; exp underflows to exact 0)
#pragma unroll
        for (int i = 0; i < 4; i++) {
            int4 mv = *(const int4*)(Mbase + (ty * 4 + i) * SEQ + kt * 64 + tx * 4);
            if (mv.x == 0) sc[i][0] = -1e30f;
            if (mv.y == 0) sc[i][1] = -1e30f;
            if (mv.z == 0) sc[i][2] = -1e30f;
            if (mv.w == 0) sc[i][3] = -1e30f;
        }

        // row max across the 16-lane tx group
        float mx[4];
#pragma unroll
        for (int i = 0; i < 4; i++) {
            mx[i] = fmaxf(fmaxf(sc[i][0], sc[i][1]), fmaxf(sc[i][2], sc[i][3]));
            for (int off = 1; off < 16; off <<= 1)
                mx[i] = fmaxf(mx[i], __shfl_xor_sync(0xffffffffu, mx[i], off));
        }

        float pr[4][4], rs[4], scl[4];
#pragma unroll
        for (int i = 0; i < 4; i++) {
            float mnew = fmaxf(m_run[i], mx[i]);
            scl[i] = __expf(m_run[i] - mnew);
            m_run[i] = mnew;
            float s0 = 0.f;
#pragma unroll
            for (int j = 0; j < 4; j++) {
                pr[i][j] = __expf(sc[i][j] - mnew);
                s0 += pr[i][j];
            }
            rs[i] = s0;
        }
#pragma unroll
        for (int i = 0; i < 4; i++) {
            for (int off = 1; off < 16; off <<= 1)
                rs[i] += __shfl_xor_sync(0xffffffffu, rs[i], off);
        }
#pragma unroll
        for (int i = 0; i < 4; i++) {
            l_run[i] = l_run[i] * scl[i] + rs[i];
#pragma unroll
            for (int j = 0; j < 4; j++) o[i][j] *= scl[i];
        }

        // stage P to smem, then O += P @ V
#pragma unroll
        for (int i = 0; i < 4; i++)
            *(float4*)&Ps[(ty * 4 + i) * PSTR + tx * 4] = *(float4*)&pr[i][0];
        __syncthreads();

#pragma unroll 16
        for (int j = 0; j < 64; j++) {
            float pv[4], vv[4];
#pragma unroll
            for (int i = 0; i < 4; i++) pv[i] = Ps[(ty * 4 + i) * PSTR + j];
            *(float4*)vv = *(float4*)&Vs[j * 64 + tx * 4];
#pragma unroll
            for (int i = 0; i < 4; i++)
#pragma unroll
                for (int jj = 0; jj < 4; jj++)
                    o[i][jj] += pv[i] * vv[jj];
        }
    }

    // epilogue: normalize and write back in [b*s][h*dk] layout
    const int h    = bh & (NH - 1);
    const int srow = qt * 64 + ty * 4;
    float* obase = Out + (b * SEQ + srow) * DM + h * DK + tx * 4;
#pragma unroll
    for (int i = 0; i < 4; i++) {
        float inv = (l_run[i] > 0.f) ? 1.f / l_run[i] : 0.f;
        float4 r;
        r.x = o[i][0] * inv;
        r.y = o[i][1] * inv;
        r.z = o[i][2] * inv;
        r.w = o[i][3] * inv;
        *(float4*)&obase[i * DM] = r;
    }
}

// ---------------- launch ----------------
extern "C" void kernel_launch(void* const* d_in, const int* in_sizes, int n_in,
                              void* d_out, int out_size)
{
    const float* q    = (const float*)d_in[0];
    const float* k    = (const float*)d_in[1];
    const float* v    = (const float*)d_in[2];
    const int*   mask = (const int*)  d_in[3];
    const float* wq   = (const float*)d_in[4];
    const float* bq   = (const float*)d_in[5];
    const float* wk   = (const float*)d_in[6];
    const float* wv   = (const float*)d_in[7];
    const float* bv   = (const float*)d_in[8];
    const float* wf   = (const float*)d_in[9];
    const float* bf   = (const float*)d_in[10];
    float* out = (float*)d_out;

    float *Qh, *KhT, *Vh, *At;
    cudaGetSymbolAddress((void**)&Qh,  g_Qh);
    cudaGetSymbolAddress((void**)&KhT, g_KhT);
    cudaGetSymbolAddress((void**)&Vh,  g_Vh);
    cudaGetSymbolAddress((void**)&At,  g_At);

    dim3 ggrid(DM / GBN, MTOT / GBM);   // (8, 32)

    gemm_kernel<<<ggrid, 256>>>(q, wq, bq,      Qh,  MTOT, DM, DM, 1);
    gemm_kernel<<<ggrid, 256>>>(k, wk, nullptr, KhT, MTOT, DM, DM, 2);
    gemm_kernel<<<ggrid, 256>>>(v, wv, bv,      Vh,  MTOT, DM, DM, 3);

    size_t smem = (3 * 64 * 64 + 64 * PSTR) * sizeof(float);  // ~65.3 KB
    cudaFuncSetAttribute(attn_kernel,
                         cudaFuncAttributeMaxDynamicSharedMemorySize, (int)smem);
    attn_kernel<<<dim3(SEQ / 64, BATCH * NH), 256, smem>>>(Qh, KhT, Vh, mask, At);

    gemm_kernel<<<ggrid, 256>>>(At, wf, bf, out, MTOT, DM, DM, 0);
}